// round 3
// baseline (speedup 1.0000x reference)
#include <cuda_runtime.h>
#include <cuda_fp16.h>
#include <stdint.h>

#define N_OUT  11008
#define K_TOT  4096
#define M_TOK  64
#define HIGH_K 1024
#define NT     64      // output columns per CTA
#define KC     64      // K per chunk (64 fp16 = 128B SW128 row)
#define NCHUNK 64
#define THREADS 512

// dynamic SMEM: two stages, each A(64x64 fp16 = 8KB) + B(64x64 fp16 = 8KB)
#define SM_BOFF 8192
#define STAGE   16384
#define SMEM_BYTES 32768

__device__ __half g_xp[M_TOK * K_TOT];   // permuted x in fp16 (scratch, 512KB)

__device__ __forceinline__ uint32_t smem_u32(const void* p) {
    uint32_t a;
    asm("{ .reg .u64 t; cvta.to.shared.u64 t, %1; cvt.u32.u64 %0, t; }" : "=r"(a) : "l"(p));
    return a;
}
__device__ __forceinline__ uint32_t swz(uint32_t o) { return o ^ ((o >> 3) & 0x70); }

__device__ __forceinline__ void ldm_x4(uint32_t& r0, uint32_t& r1, uint32_t& r2, uint32_t& r3,
                                       uint32_t addr) {
    asm volatile("ldmatrix.sync.aligned.m8n8.x4.shared.b16 {%0,%1,%2,%3}, [%4];"
                 : "=r"(r0), "=r"(r1), "=r"(r2), "=r"(r3) : "r"(addr));
}
__device__ __forceinline__ void mma16816(float& c0, float& c1, float& c2, float& c3,
                                         uint32_t a0, uint32_t a1, uint32_t a2, uint32_t a3,
                                         uint32_t b0, uint32_t b1) {
    asm volatile("mma.sync.aligned.m16n8k16.row.col.f32.f16.f16.f32 "
                 "{%0,%1,%2,%3}, {%4,%5,%6,%7}, {%8,%9}, {%0,%1,%2,%3};"
                 : "+f"(c0), "+f"(c1), "+f"(c2), "+f"(c3)
                 : "r"(a0), "r"(a1), "r"(a2), "r"(a3), "r"(b0), "r"(b1));
}

// ---------------- prep: x_perm -> fp16 ----------------
__global__ void prep_kernel(const float* __restrict__ x, const int* __restrict__ ci) {
    int idx = blockIdx.x * blockDim.x + threadIdx.x;   // 64*4096 threads exactly
    int m = idx >> 12;
    int k = idx & 4095;
    g_xp[idx] = __float2half_rn(x[(m << 12) + ci[k]]);
}

// ---------------- main fused dequant + mma.sync GEMM ----------------
__global__ void __launch_bounds__(THREADS, 2) gemm_kernel(
    const int* __restrict__ Wh, const int* __restrict__ Wl,
    const float* __restrict__ sh, const float* __restrict__ sl,
    const float* __restrict__ bias, float* __restrict__ out)
{
    extern __shared__ char smem[];
    const uint32_t sb = smem_u32(smem);
    const int tid = threadIdx.x;
    const int n0 = blockIdx.x * NT;

    const int lane = tid & 31;
    const int wid  = tid >> 5;          // 0..15
    const int wm   = wid & 3;           // warp m-tile (16 rows)
    const int wn   = wid >> 2;          // warp n-tile (16 cols)

    // ldmatrix per-lane base offsets (unswizzled; swizzle applied per k-step)
    const int sub = lane >> 3;
    const uint32_t offA = (uint32_t)((wm * 16 + (sub & 1) * 8 + (lane & 7)) * 128 + (sub >> 1) * 16);
    const uint32_t offB = (uint32_t)((wn * 16 + (sub >> 1) * 8 + (lane & 7)) * 128 + (sub & 1) * 16);

    // dequant / A-copy work split
    const int am  = tid >> 3;   // A: row 0..63
    const int akb = tid & 7;    // A: 16B block within 128B row
    const int bn  = tid & 63;   // B: local n
    const int gc  = n0 + bn;    // global column

    // register-prefetch state
    uint4 ra;
    int w0, w1, w2, w3, w4, w5;
    float rs;

    // prologue: load chunk 0 (6-bit high region)
    {
        ra = *(const uint4*)(g_xp + (am << 12) + (akb << 3));
        int qi0 = tid >> 6;            // quad 0..7 (second task = qi0+8)
        int pr0 = 3 * qi0;
        int pr1 = pr0 + 24;
        w0 = Wh[(pr0 + 0) * N_OUT + gc];
        w1 = Wh[(pr0 + 1) * N_OUT + gc];
        w2 = Wh[(pr0 + 2) * N_OUT + gc];
        w3 = Wh[(pr1 + 0) * N_OUT + gc];
        w4 = Wh[(pr1 + 1) * N_OUT + gc];
        w5 = Wh[(pr1 + 2) * N_OUT + gc];
        rs = sh[gc];
    }

    float acc[2][4];
    #pragma unroll
    for (int t = 0; t < 2; ++t)
        #pragma unroll
        for (int i = 0; i < 4; ++i) acc[t][i] = 0.0f;

    for (int c = 0; c < NCHUNK; ++c) {
        const int buf = c & 1;
        const uint32_t aoff = (uint32_t)(buf * STAGE);
        const uint32_t boff = aoff + SM_BOFF;

        // ---- store phase (held registers -> SMEM tiles) ----
        *(uint4*)(smem + aoff + swz((uint32_t)(am * 128 + akb * 16))) = ra;

        if (c < 16) {  // 6-bit region: two quads per thread
            int qi0 = tid >> 6;
            float s = rs;
            {
                int v0 = w0 & 63;
                int v1 = ((w0 >> 6) & 3) | ((w1 & 15) << 2);
                int v2 = ((w1 >> 4) & 15) | ((w2 & 3) << 4);
                int v3 = (w2 >> 2) & 63;
                __half2 h01 = __floats2half2_rn((float)(v0 - 31) * s, (float)(v1 - 31) * s);
                __half2 h23 = __floats2half2_rn((float)(v2 - 31) * s, (float)(v3 - 31) * s);
                uint2 val;
                val.x = *reinterpret_cast<uint32_t*>(&h01);
                val.y = *reinterpret_cast<uint32_t*>(&h23);
                *(uint2*)(smem + boff + swz((uint32_t)(bn * 128 + qi0 * 8))) = val;
            }
            {
                int v0 = w3 & 63;
                int v1 = ((w3 >> 6) & 3) | ((w4 & 15) << 2);
                int v2 = ((w4 >> 4) & 15) | ((w5 & 3) << 4);
                int v3 = (w5 >> 2) & 63;
                __half2 h01 = __floats2half2_rn((float)(v0 - 31) * s, (float)(v1 - 31) * s);
                __half2 h23 = __floats2half2_rn((float)(v2 - 31) * s, (float)(v3 - 31) * s);
                uint2 val;
                val.x = *reinterpret_cast<uint32_t*>(&h01);
                val.y = *reinterpret_cast<uint32_t*>(&h23);
                *(uint2*)(smem + boff + swz((uint32_t)(bn * 128 + (qi0 + 8) * 8))) = val;
            }
        } else {       // 5-bit region: one octet per thread
            int oi = tid >> 6;
            float s = rs;
            int v0 = w0 & 31;
            int v1 = ((w0 >> 5) & 7) | ((w1 & 3) << 3);
            int v2 = (w1 >> 2) & 31;
            int v3 = ((w1 >> 7) & 1) | ((w2 & 15) << 1);
            int v4 = ((w2 >> 4) & 15) | ((w3 & 1) << 4);
            int v5 = (w3 >> 1) & 31;
            int v6 = ((w3 >> 6) & 3) | ((w4 & 7) << 2);
            int v7 = (w4 >> 3) & 31;
            __half2 p0 = __floats2half2_rn((float)(v0 - 15) * s, (float)(v1 - 15) * s);
            __half2 p1 = __floats2half2_rn((float)(v2 - 15) * s, (float)(v3 - 15) * s);
            __half2 p2 = __floats2half2_rn((float)(v4 - 15) * s, (float)(v5 - 15) * s);
            __half2 p3 = __floats2half2_rn((float)(v6 - 15) * s, (float)(v7 - 15) * s);
            uint4 val;
            val.x = *reinterpret_cast<uint32_t*>(&p0);
            val.y = *reinterpret_cast<uint32_t*>(&p1);
            val.z = *reinterpret_cast<uint32_t*>(&p2);
            val.w = *reinterpret_cast<uint32_t*>(&p3);
            *(uint4*)(smem + boff + swz((uint32_t)(bn * 128 + oi * 16))) = val;
        }
        __syncthreads();

        // ---- prefetch next chunk into registers (in flight during mma) ----
        if (c + 1 < NCHUNK) {
            int cn = c + 1;
            int k0 = cn * KC;
            ra = *(const uint4*)(g_xp + (am << 12) + k0 + (akb << 3));
            if (cn < 16) {
                int qi0 = tid >> 6;
                int pr0 = 48 * cn + 3 * qi0;
                int pr1 = pr0 + 24;
                w0 = Wh[(pr0 + 0) * N_OUT + gc];
                w1 = Wh[(pr0 + 1) * N_OUT + gc];
                w2 = Wh[(pr0 + 2) * N_OUT + gc];
                w3 = Wh[(pr1 + 0) * N_OUT + gc];
                w4 = Wh[(pr1 + 1) * N_OUT + gc];
                w5 = Wh[(pr1 + 2) * N_OUT + gc];
                rs = sh[(k0 >> 7) * N_OUT + gc];
            } else {
                int oi = tid >> 6;
                int pr = 40 * (cn - 16) + 5 * oi;
                w0 = Wl[(pr + 0) * N_OUT + gc];
                w1 = Wl[(pr + 1) * N_OUT + gc];
                w2 = Wl[(pr + 2) * N_OUT + gc];
                w3 = Wl[(pr + 3) * N_OUT + gc];
                w4 = Wl[(pr + 4) * N_OUT + gc];
                rs = sl[((k0 - HIGH_K) >> 7) * N_OUT + gc];
            }
        }

        // ---- mma phase: 4 k-steps, each ldmatrix x4 A + x4 B + 2 mma ----
        #pragma unroll
        for (int ks = 0; ks < 4; ++ks) {
            uint32_t a0, a1, a2, a3, b0, b1, b2, b3;
            ldm_x4(a0, a1, a2, a3, sb + aoff + swz(offA + (uint32_t)(ks * 32)));
            ldm_x4(b0, b1, b2, b3, sb + boff + swz(offB + (uint32_t)(ks * 32)));
            mma16816(acc[0][0], acc[0][1], acc[0][2], acc[0][3], a0, a1, a2, a3, b0, b1);
            mma16816(acc[1][0], acc[1][1], acc[1][2], acc[1][3], a0, a1, a2, a3, b2, b3);
        }
        // double buffer: next store targets the other stage; the stage written
        // two iterations from now was fully consumed before the NEXT sync.
        __syncthreads();
    }

    // ---- epilogue: acc regs -> gmem with bias ----
    // d0,d1: row = m0 + lane/4, cols = nb + (lane%4)*2 + {0,1}
    // d2,d3: row = m0 + lane/4 + 8
    const int r0 = wm * 16 + (lane >> 2);
    #pragma unroll
    for (int nt = 0; nt < 2; ++nt) {
        const int nb = n0 + wn * 16 + nt * 8 + (lane & 3) * 2;
        const float2 bb = *(const float2*)(bias + nb);
        float2 o;
        o.x = acc[nt][0] + bb.x;
        o.y = acc[nt][1] + bb.y;
        *(float2*)(out + r0 * N_OUT + nb) = o;
        o.x = acc[nt][2] + bb.x;
        o.y = acc[nt][3] + bb.y;
        *(float2*)(out + (r0 + 8) * N_OUT + nb) = o;
    }
}

extern "C" void kernel_launch(void* const* d_in, const int* in_sizes, int n_in,
                              void* d_out, int out_size) {
    const float* x    = (const float*)d_in[0];
    const int*   Wh   = (const int*)d_in[1];
    const int*   Wl   = (const int*)d_in[2];
    const float* sh   = (const float*)d_in[3];
    const float* sl   = (const float*)d_in[4];
    const int*   ci   = (const int*)d_in[5];
    const float* bias = (const float*)d_in[6];
    float* out = (float*)d_out;

    cudaFuncSetAttribute(gemm_kernel, cudaFuncAttributeMaxDynamicSharedMemorySize, SMEM_BYTES);

    prep_kernel<<<(M_TOK * K_TOT) / 256, 256>>>(x, ci);
    gemm_kernel<<<N_OUT / NT, THREADS, SMEM_BYTES>>>(Wh, Wl, sh, sl, bias, out);
}